// round 1
// baseline (speedup 1.0000x reference)
#include <cuda_runtime.h>
#include <math.h>

// Problem dims (fixed by the reference)
#define BB 8
#define SS 2048
#define DD 1024
#define MTOT (BB * SS)   // 16384

// SGEMM tile config
#define BM 128
#define BN 128
#define BK 8
#define TM 8
#define TN 8
#define NTHREADS 256

// -------- scratch (static device globals; no allocation allowed) --------
__device__ float g_q[(size_t)MTOT * DD];      // 64 MB
__device__ float g_k[(size_t)MTOT * DD];      // 64 MB
__device__ float g_v[(size_t)MTOT * DD];      // 64 MB
__device__ float g_g[(size_t)MTOT * DD];      // 64 MB (sigmoid gate)
__device__ float g_s[(size_t)BB * SS * SS];   // 128 MB (scores / attn)
__device__ float g_c[(size_t)MTOT * DD];      // 64 MB (context * gate)

// ============================================================
// GEMM NN: C[M,N] = A[M,K] @ B[K,N] + bias[N]  (act=1 -> sigmoid)
// ============================================================
__global__ __launch_bounds__(NTHREADS)
void sgemm_nn(const float* __restrict__ A, const float* __restrict__ Bm,
              const float* __restrict__ bias, float* __restrict__ C,
              int M, int N, int K, int act)
{
    __shared__ float As[BK][BM];
    __shared__ float Bs[BK][BN];

    const int tid  = threadIdx.x;
    const int bx   = blockIdx.x;   // N tile
    const int by   = blockIdx.y;   // M tile

    const int tcol = tid % (BN / TN);   // 0..15
    const int trow = tid / (BN / TN);   // 0..15

    // A loads: 128 rows x 8 cols = 1024 floats = 256 threads x 1 float4
    const int aRow = tid / (BK / 4);          // 0..127
    const int aCol = (tid % (BK / 4)) * 4;    // 0 or 4
    // B loads: 8 rows x 128 cols = 256 threads x 1 float4
    const int bRow = tid / (BN / 4);          // 0..7
    const int bCol = (tid % (BN / 4)) * 4;    // 0..124

    const float* Ap = A + (size_t)(by * BM) * K;

    float acc[TM][TN];
#pragma unroll
    for (int i = 0; i < TM; i++)
#pragma unroll
        for (int j = 0; j < TN; j++) acc[i][j] = 0.0f;

    for (int k0 = 0; k0 < K; k0 += BK) {
        float4 a4 = *(const float4*)(Ap + (size_t)aRow * K + k0 + aCol);
        As[aCol + 0][aRow] = a4.x;
        As[aCol + 1][aRow] = a4.y;
        As[aCol + 2][aRow] = a4.z;
        As[aCol + 3][aRow] = a4.w;
        float4 b4 = *(const float4*)(Bm + (size_t)(k0 + bRow) * N + bx * BN + bCol);
        *(float4*)&Bs[bRow][bCol] = b4;
        __syncthreads();
#pragma unroll
        for (int kk = 0; kk < BK; kk++) {
            float ra[TM], rb[TN];
#pragma unroll
            for (int i = 0; i < TM; i++) ra[i] = As[kk][trow * TM + i];
#pragma unroll
            for (int j = 0; j < TN; j++) rb[j] = Bs[kk][tcol * TN + j];
#pragma unroll
            for (int i = 0; i < TM; i++)
#pragma unroll
                for (int j = 0; j < TN; j++) acc[i][j] += ra[i] * rb[j];
        }
        __syncthreads();
    }

#pragma unroll
    for (int i = 0; i < TM; i++) {
        int row = by * BM + trow * TM + i;
#pragma unroll
        for (int j = 0; j < TN; j++) {
            int col = bx * BN + tcol * TN + j;
            float v = acc[i][j] + bias[col];
            if (act) v = 1.0f / (1.0f + expf(-v));
            C[(size_t)row * N + col] = v;
        }
    }
}

// ============================================================
// Batched NT: scores[b][i][j] = sum_d q[b,i,d] * k[b,j,d]
// grid.z = batch; M=N=SS, K=DD
// ============================================================
__global__ __launch_bounds__(NTHREADS)
void sgemm_nt_batched(const float* __restrict__ Q, const float* __restrict__ Km,
                      float* __restrict__ Sc)
{
    __shared__ float As[BK][BM];
    __shared__ float Bs[BK][BN];

    const int tid = threadIdx.x;
    const int bx  = blockIdx.x;
    const int by  = blockIdx.y;
    const int b   = blockIdx.z;

    const int tcol = tid % (BN / TN);
    const int trow = tid / (BN / TN);

    const int aRow = tid / (BK / 4);
    const int aCol = (tid % (BK / 4)) * 4;

    const float* Ap = Q  + (size_t)b * SS * DD + (size_t)(by * BM) * DD;
    const float* Bp = Km + (size_t)b * SS * DD + (size_t)(bx * BN) * DD;
    float* Cp = Sc + (size_t)b * SS * SS;

    float acc[TM][TN];
#pragma unroll
    for (int i = 0; i < TM; i++)
#pragma unroll
        for (int j = 0; j < TN; j++) acc[i][j] = 0.0f;

    for (int k0 = 0; k0 < DD; k0 += BK) {
        float4 a4 = *(const float4*)(Ap + (size_t)aRow * DD + k0 + aCol);
        As[aCol + 0][aRow] = a4.x;
        As[aCol + 1][aRow] = a4.y;
        As[aCol + 2][aRow] = a4.z;
        As[aCol + 3][aRow] = a4.w;
        // B tile: rows of Km (N dim), cols along K -> transpose into Bs[k][n]
        float4 b4 = *(const float4*)(Bp + (size_t)aRow * DD + k0 + aCol);
        Bs[aCol + 0][aRow] = b4.x;
        Bs[aCol + 1][aRow] = b4.y;
        Bs[aCol + 2][aRow] = b4.z;
        Bs[aCol + 3][aRow] = b4.w;
        __syncthreads();
#pragma unroll
        for (int kk = 0; kk < BK; kk++) {
            float ra[TM], rb[TN];
#pragma unroll
            for (int i = 0; i < TM; i++) ra[i] = As[kk][trow * TM + i];
#pragma unroll
            for (int j = 0; j < TN; j++) rb[j] = Bs[kk][tcol * TN + j];
#pragma unroll
            for (int i = 0; i < TM; i++)
#pragma unroll
                for (int j = 0; j < TN; j++) acc[i][j] += ra[i] * rb[j];
        }
        __syncthreads();
    }

#pragma unroll
    for (int i = 0; i < TM; i++) {
        int row = by * BM + trow * TM + i;
#pragma unroll
        for (int j = 0; j < TN; j++) {
            int col = bx * BN + tcol * TN + j;
            Cp[(size_t)row * SS + col] = acc[i][j];
        }
    }
}

// ============================================================
// Row softmax, in place. One block per row of length SS.
// ============================================================
__global__ __launch_bounds__(256)
void softmax_rows(float* __restrict__ Sc)
{
    __shared__ float red[256];
    const int row = blockIdx.x;
    const int tid = threadIdx.x;
    float* p = Sc + (size_t)row * SS;

    // max
    float m = -INFINITY;
    for (int j = tid; j < SS; j += 256) m = fmaxf(m, p[j]);
    red[tid] = m;
    __syncthreads();
    for (int s = 128; s > 0; s >>= 1) {
        if (tid < s) red[tid] = fmaxf(red[tid], red[tid + s]);
        __syncthreads();
    }
    m = red[0];
    __syncthreads();

    // exp + sum
    float sum = 0.0f;
    for (int j = tid; j < SS; j += 256) {
        float e = expf(p[j] - m);
        p[j] = e;
        sum += e;
    }
    red[tid] = sum;
    __syncthreads();
    for (int s = 128; s > 0; s >>= 1) {
        if (tid < s) red[tid] += red[tid + s];
        __syncthreads();
    }
    float inv = 1.0f / red[0];
    __syncthreads();

    for (int j = tid; j < SS; j += 256) p[j] *= inv;
}

// ============================================================
// Batched NN with gate epilogue:
//   ctx[b,i,d] = (sum_j P[b,i,j] * v[b,j,d]) * gate[b,i,d]
// grid.z = batch; M=SS, N=DD, K=SS
// ============================================================
__global__ __launch_bounds__(NTHREADS)
void sgemm_nn_batched_gate(const float* __restrict__ P, const float* __restrict__ V,
                           const float* __restrict__ G, float* __restrict__ C)
{
    __shared__ float As[BK][BM];
    __shared__ float Bs[BK][BN];

    const int tid = threadIdx.x;
    const int bx  = blockIdx.x;
    const int by  = blockIdx.y;
    const int b   = blockIdx.z;

    const int tcol = tid % (BN / TN);
    const int trow = tid / (BN / TN);

    const int aRow = tid / (BK / 4);
    const int aCol = (tid % (BK / 4)) * 4;
    const int bRow = tid / (BN / 4);
    const int bCol = (tid % (BN / 4)) * 4;

    const float* Ap = P + (size_t)b * SS * SS + (size_t)(by * BM) * SS;
    const float* Bp = V + (size_t)b * SS * DD;
    const float* Gp = G + (size_t)b * SS * DD;
    float* Cp = C + (size_t)b * SS * DD;

    float acc[TM][TN];
#pragma unroll
    for (int i = 0; i < TM; i++)
#pragma unroll
        for (int j = 0; j < TN; j++) acc[i][j] = 0.0f;

    for (int k0 = 0; k0 < SS; k0 += BK) {
        float4 a4 = *(const float4*)(Ap + (size_t)aRow * SS + k0 + aCol);
        As[aCol + 0][aRow] = a4.x;
        As[aCol + 1][aRow] = a4.y;
        As[aCol + 2][aRow] = a4.z;
        As[aCol + 3][aRow] = a4.w;
        float4 b4 = *(const float4*)(Bp + (size_t)(k0 + bRow) * DD + bx * BN + bCol);
        *(float4*)&Bs[bRow][bCol] = b4;
        __syncthreads();
#pragma unroll
        for (int kk = 0; kk < BK; kk++) {
            float ra[TM], rb[TN];
#pragma unroll
            for (int i = 0; i < TM; i++) ra[i] = As[kk][trow * TM + i];
#pragma unroll
            for (int j = 0; j < TN; j++) rb[j] = Bs[kk][tcol * TN + j];
#pragma unroll
            for (int i = 0; i < TM; i++)
#pragma unroll
                for (int j = 0; j < TN; j++) acc[i][j] += ra[i] * rb[j];
        }
        __syncthreads();
    }

#pragma unroll
    for (int i = 0; i < TM; i++) {
        int row = by * BM + trow * TM + i;
#pragma unroll
        for (int j = 0; j < TN; j++) {
            int col = bx * BN + tcol * TN + j;
            size_t off = (size_t)row * DD + col;
            Cp[off] = acc[i][j] * Gp[off];
        }
    }
}

// ============================================================
// launch
// ============================================================
extern "C" void kernel_launch(void* const* d_in, const int* in_sizes, int n_in,
                              void* d_out, int out_size)
{
    const float* queries = (const float*)d_in[0];
    const float* keys    = (const float*)d_in[1];
    const float* values  = (const float*)d_in[2];
    const float* Wq = (const float*)d_in[3];
    const float* bq = (const float*)d_in[4];
    const float* Wk = (const float*)d_in[5];
    const float* bk = (const float*)d_in[6];
    const float* Wv = (const float*)d_in[7];
    const float* bv = (const float*)d_in[8];
    const float* Wg = (const float*)d_in[9];
    const float* bg = (const float*)d_in[10];
    const float* Wo = (const float*)d_in[11];
    const float* bo = (const float*)d_in[12];
    float* out = (float*)d_out;

    float *q, *k, *v, *g, *sc, *ctx;
    cudaGetSymbolAddress((void**)&q,   g_q);
    cudaGetSymbolAddress((void**)&k,   g_k);
    cudaGetSymbolAddress((void**)&v,   g_v);
    cudaGetSymbolAddress((void**)&g,   g_g);
    cudaGetSymbolAddress((void**)&sc,  g_s);
    cudaGetSymbolAddress((void**)&ctx, g_c);

    dim3 blk(NTHREADS);
    dim3 gridProj(DD / BN, MTOT / BM);      // 8 x 128
    // Projections: q, k, v, gate(sigmoid)
    sgemm_nn<<<gridProj, blk>>>(queries, Wq, bq, q, MTOT, DD, DD, 0);
    sgemm_nn<<<gridProj, blk>>>(keys,    Wk, bk, k, MTOT, DD, DD, 0);
    sgemm_nn<<<gridProj, blk>>>(values,  Wv, bv, v, MTOT, DD, DD, 0);
    sgemm_nn<<<gridProj, blk>>>(queries, Wg, bg, g, MTOT, DD, DD, 1);

    // Scores: q @ k^T per batch
    dim3 gridSc(SS / BN, SS / BM, BB);      // 16 x 16 x 8
    sgemm_nt_batched<<<gridSc, blk>>>(q, k, sc);

    // Softmax over rows
    softmax_rows<<<BB * SS, 256>>>(sc);

    // Context = attn @ v, gated
    dim3 gridCtx(DD / BN, SS / BM, BB);     // 8 x 16 x 8
    sgemm_nn_batched_gate<<<gridCtx, blk>>>(sc, v, g, ctx);

    // Output projection
    sgemm_nn<<<gridProj, blk>>>(ctx, Wo, bo, out, MTOT, DD, DD, 0);
}

// round 3
// speedup vs baseline: 2.8443x; 2.8443x over previous
#include <cuda_runtime.h>
#include <cuda_fp16.h>
#include <stdint.h>
#include <math.h>

typedef __half fp16;

#define BB 8
#define SEQ 2048
#define DDIM 1024
#define MTOT (BB * SEQ)   // 16384

// ------------------------------------------------------------------
// PTX helpers (sm_80+ features only — no arch-'a' instructions)
// ------------------------------------------------------------------
__device__ __forceinline__ uint32_t smem_u32(const void* p) {
    uint32_t a;
    asm("{ .reg .u64 t; cvta.to.shared.u64 t, %1; cvt.u32.u64 %0, t; }"
        : "=r"(a) : "l"(p));
    return a;
}
#define CP16(dst, src) \
    asm volatile("cp.async.cg.shared.global [%0], [%1], 16;" :: "r"(dst), "l"(src))
#define CP_COMMIT() asm volatile("cp.async.commit_group;" ::: "memory")
#define CP_WAIT2()  asm volatile("cp.async.wait_group 2;" ::: "memory")

__device__ __forceinline__ void ldmx4(uint32_t* r, uint32_t addr) {
    asm volatile("ldmatrix.sync.aligned.m8n8.x4.shared.b16 {%0,%1,%2,%3}, [%4];"
        : "=r"(r[0]), "=r"(r[1]), "=r"(r[2]), "=r"(r[3]) : "r"(addr));
}
__device__ __forceinline__ void mma16816(float* c, const uint32_t* a, const uint32_t* b) {
    asm volatile(
        "mma.sync.aligned.m16n8k16.row.col.f32.f16.f16.f32 "
        "{%0,%1,%2,%3}, {%4,%5,%6,%7}, {%8,%9}, {%0,%1,%2,%3};"
        : "+f"(c[0]), "+f"(c[1]), "+f"(c[2]), "+f"(c[3])
        : "r"(a[0]), "r"(a[1]), "r"(a[2]), "r"(a[3]), "r"(b[0]), "r"(b[1]));
}

// ------------------------------------------------------------------
// Scratch (static device globals; allocation forbidden)
// ------------------------------------------------------------------
__device__ fp16 g_iqh[(size_t)MTOT * DDIM], g_iql[(size_t)MTOT * DDIM];
__device__ fp16 g_ikh[(size_t)MTOT * DDIM], g_ikl[(size_t)MTOT * DDIM];
__device__ fp16 g_ivh[(size_t)MTOT * DDIM], g_ivl[(size_t)MTOT * DDIM];
__device__ fp16 g_wt[5][2][(size_t)DDIM * DDIM];
__device__ fp16 g_qh[(size_t)MTOT * DDIM], g_ql[(size_t)MTOT * DDIM];
__device__ fp16 g_kh[(size_t)MTOT * DDIM], g_kl[(size_t)MTOT * DDIM];
__device__ float g_v[(size_t)MTOT * DDIM];
__device__ fp16 g_vth[(size_t)BB * DDIM * SEQ], g_vtl[(size_t)BB * DDIM * SEQ];
__device__ float g_gate[(size_t)MTOT * DDIM];
__device__ float g_sc[(size_t)BB * SEQ * SEQ];
__device__ fp16 g_ph[(size_t)BB * SEQ * SEQ], g_pl[(size_t)BB * SEQ * SEQ];
__device__ fp16 g_ch[(size_t)MTOT * DDIM], g_cl[(size_t)MTOT * DDIM];

// ------------------------------------------------------------------
// Elementwise split: fp32 -> hi(fp16), lo(fp16)
// ------------------------------------------------------------------
__global__ __launch_bounds__(256)
void split_f32(const float* __restrict__ x, fp16* __restrict__ h,
               fp16* __restrict__ l, size_t n)
{
    size_t i = ((size_t)blockIdx.x * 256 + threadIdx.x) * 4;
    if (i >= n) return;
    float4 v = *(const float4*)(x + i);
    fp16 h0 = __float2half(v.x), h1 = __float2half(v.y);
    fp16 h2 = __float2half(v.z), h3 = __float2half(v.w);
    __half2 hh0, hh1, ll0, ll1;
    hh0.x = h0; hh0.y = h1; hh1.x = h2; hh1.y = h3;
    ll0.x = __float2half(v.x - __half2float(h0));
    ll0.y = __float2half(v.y - __half2float(h1));
    ll1.x = __float2half(v.z - __half2float(h2));
    ll1.y = __float2half(v.w - __half2float(h3));
    *(__half2*)(h + i)     = hh0;
    *(__half2*)(h + i + 2) = hh1;
    *(__half2*)(l + i)     = ll0;
    *(__half2*)(l + i + 2) = ll1;
}

// ------------------------------------------------------------------
// Transpose + split: src [R,C] fp32 -> dst [C,R] hi/lo fp16 (batched)
// ------------------------------------------------------------------
__global__ __launch_bounds__(256)
void transpose_split(const float* __restrict__ src, fp16* __restrict__ dh,
                     fp16* __restrict__ dl, int R, int C,
                     long long sb, long long db)
{
    __shared__ float t[32][33];
    src += (long long)blockIdx.z * sb;
    dh  += (long long)blockIdx.z * db;
    dl  += (long long)blockIdx.z * db;
    int r0 = blockIdx.y * 32, c0 = blockIdx.x * 32;
#pragma unroll
    for (int i = 0; i < 32; i += 8)
        t[threadIdx.y + i][threadIdx.x] =
            src[(size_t)(r0 + threadIdx.y + i) * C + c0 + threadIdx.x];
    __syncthreads();
#pragma unroll
    for (int i = 0; i < 32; i += 8) {
        int cc = c0 + threadIdx.y + i;
        int rr = r0 + threadIdx.x;
        float v = t[threadIdx.x][threadIdx.y + i];
        fp16 h = __float2half(v);
        dh[(size_t)cc * R + rr] = h;
        dl[(size_t)cc * R + rr] = __float2half(v - __half2float(h));
    }
}

// ------------------------------------------------------------------
// Row softmax: fp32 scores -> fp16 hi/lo split P
// ------------------------------------------------------------------
__global__ __launch_bounds__(256)
void softmax_split(const float* __restrict__ Sc, fp16* __restrict__ Ph,
                   fp16* __restrict__ Pl)
{
    __shared__ float red[256];
    const size_t row = blockIdx.x;
    const int tid = threadIdx.x;
    const float* p = Sc + row * SEQ;

    float m = -INFINITY;
    for (int j = tid; j < SEQ; j += 256) m = fmaxf(m, p[j]);
    red[tid] = m; __syncthreads();
    for (int s = 128; s > 0; s >>= 1) {
        if (tid < s) red[tid] = fmaxf(red[tid], red[tid + s]);
        __syncthreads();
    }
    m = red[0]; __syncthreads();

    float sum = 0.0f;
    for (int j = tid; j < SEQ; j += 256) sum += __expf(p[j] - m);
    red[tid] = sum; __syncthreads();
    for (int s = 128; s > 0; s >>= 1) {
        if (tid < s) red[tid] += red[tid + s];
        __syncthreads();
    }
    float inv = 1.0f / red[0];

    for (int j = tid; j < SEQ; j += 256) {
        float e = __expf(p[j] - m) * inv;
        fp16 h = __float2half(e);
        Ph[row * SEQ + j] = h;
        Pl[row * SEQ + j] = __float2half(e - __half2float(h));
    }
}

// ------------------------------------------------------------------
// mma.sync fp16x3 GEMM: C[M,N] = A[M,K] @ B[N,K]^T (both K-major splits)
// CTA 128x128, BK=64 chunk, 3-stage cp.async, 8 warps (4M x 2N),
// warp tile 32x64, m16n8k16, fp32 register accumulators.
// epi: 0=fp32, 1=bias fp32, 2=bias+split, 3=bias+sigmoid fp32, 4=gate*split
// ------------------------------------------------------------------
#define STAGES 3
#define STAGE_BYTES 32768
#define GEMM_SMEM (STAGES * STAGE_BYTES)

__global__ __launch_bounds__(256, 2)
void gemm3(const fp16* __restrict__ Ah, const fp16* __restrict__ Al,
           const fp16* __restrict__ Bh, const fp16* __restrict__ Bl,
           long long sAb, long long sBb, int K,
           float* __restrict__ Cf, fp16* __restrict__ Coh, fp16* __restrict__ Col,
           int ldc, long long sCb,
           const float* __restrict__ bias, const float* __restrict__ gate,
           long long sGb, int epi)
{
    extern __shared__ char dsm[];
    const uint32_t sbase = smem_u32(dsm);

    const int tid  = threadIdx.x;
    const int wid  = tid >> 5;
    const int lane = tid & 31;
    const int wm = wid >> 1;          // 0..3
    const int wn = wid & 1;           // 0..1
    const int z  = blockIdx.z;
    Ah += (long long)z * sAb; Al += (long long)z * sAb;
    Bh += (long long)z * sBb; Bl += (long long)z * sBb;

    const int m0 = blockIdx.y * 128;
    const int n0 = blockIdx.x * 128;
    const int KC = K >> 6;
    const int NC = 3 * KC;

    // cp.async slots: 4 x 16B per tile per thread
    int rows[4], cols[4];
    uint32_t soff[4];
#pragma unroll
    for (int i = 0; i < 4; i++) {
        int idx = tid + i * 256;
        rows[i] = idx >> 3;
        cols[i] = idx & 7;
        soff[i] = (uint32_t)(rows[i] * 128 + ((cols[i] ^ (rows[i] & 7)) << 4));
    }

    auto load_chunk = [&](int c, int stage) {
        int phase = c / KC;
        int inner = c - phase * KC;
        const fp16* As = (phase == 1) ? Al : Ah;
        const fp16* Bs = (phase == 2) ? Bl : Bh;
        uint32_t aB = sbase + (uint32_t)stage * STAGE_BYTES;
        uint32_t bB = aB + 16384u;
#pragma unroll
        for (int i = 0; i < 4; i++)
            CP16(aB + soff[i], As + (size_t)(m0 + rows[i]) * K + inner * 64 + cols[i] * 8);
#pragma unroll
        for (int i = 0; i < 4; i++)
            CP16(bB + soff[i], Bs + (size_t)(n0 + rows[i]) * K + inner * 64 + cols[i] * 8);
    };

    for (int s = 0; s < STAGES; s++) { load_chunk(s, s); CP_COMMIT(); }

    float acc[2][8][4];
#pragma unroll
    for (int mt = 0; mt < 2; mt++)
#pragma unroll
        for (int nt = 0; nt < 8; nt++)
#pragma unroll
            for (int r = 0; r < 4; r++) acc[mt][nt][r] = 0.0f;

    // ldmatrix row bases (SMEM rows are CTA-tile-relative)
    const int aRowBase = wm * 32 + (lane & 15);
    const int bRowBase = wn * 64 + (lane & 15);
    const int khalf    = lane >> 4;   // 0/1: which k8 of the k16

    for (int c = 0; c < NC; c++) {
        const int st = c % STAGES;
        CP_WAIT2();
        __syncthreads();
        const uint32_t aB = sbase + (uint32_t)st * STAGE_BYTES;
        const uint32_t bB = aB + 16384u;
#pragma unroll
        for (int ks = 0; ks < 4; ks++) {
            const int ch = 2 * ks + khalf;
            uint32_t afr[2][4];
#pragma unroll
            for (int mt = 0; mt < 2; mt++) {
                int r = aRowBase + mt * 16;
                ldmx4(afr[mt], aB + (uint32_t)(r * 128 + ((ch ^ (r & 7)) << 4)));
            }
            uint32_t bfr[8][2];
#pragma unroll
            for (int nb = 0; nb < 4; nb++) {
                int r = bRowBase + nb * 16;
                uint32_t t4[4];
                ldmx4(t4, bB + (uint32_t)(r * 128 + ((ch ^ (r & 7)) << 4)));
                bfr[nb * 2][0]     = t4[0];
                bfr[nb * 2][1]     = t4[2];
                bfr[nb * 2 + 1][0] = t4[1];
                bfr[nb * 2 + 1][1] = t4[3];
            }
#pragma unroll
            for (int mt = 0; mt < 2; mt++)
#pragma unroll
                for (int nt = 0; nt < 8; nt++)
                    mma16816(acc[mt][nt], afr[mt], bfr[nt]);
        }
        __syncthreads();
        if (c + STAGES < NC) load_chunk(c + STAGES, st);
        CP_COMMIT();
    }

    // ---------------- epilogue (register accumulators) ----------------
    const int erow0 = m0 + wm * 32 + (lane >> 2);
    const int ecol0 = n0 + wn * 64 + (lane & 3) * 2;

#pragma unroll
    for (int mt = 0; mt < 2; mt++) {
#pragma unroll
        for (int rr = 0; rr < 2; rr++) {
            const int row = erow0 + mt * 16 + rr * 8;
#pragma unroll
            for (int nt = 0; nt < 8; nt++) {
                const int col = ecol0 + nt * 8;
                float v0 = acc[mt][nt][2 * rr];
                float v1 = acc[mt][nt][2 * rr + 1];
                const size_t off = (size_t)z * sCb + (size_t)row * ldc + col;
                if (epi == 0) {
                    *(float2*)(Cf + off) = make_float2(v0, v1);
                } else if (epi == 1 || epi == 3) {
                    v0 += bias[col]; v1 += bias[col + 1];
                    if (epi == 3) {
                        v0 = 1.0f / (1.0f + __expf(-v0));
                        v1 = 1.0f / (1.0f + __expf(-v1));
                    }
                    *(float2*)(Cf + off) = make_float2(v0, v1);
                } else {
                    if (epi == 2) {
                        v0 += bias[col]; v1 += bias[col + 1];
                    } else {
                        float2 gg = *(const float2*)(gate + (size_t)z * sGb +
                                                     (size_t)row * ldc + col);
                        v0 *= gg.x; v1 *= gg.y;
                    }
                    fp16 h0 = __float2half(v0), h1 = __float2half(v1);
                    __half2 hh, ll;
                    hh.x = h0; hh.y = h1;
                    ll.x = __float2half(v0 - __half2float(h0));
                    ll.y = __float2half(v1 - __half2float(h1));
                    *(__half2*)(Coh + off) = hh;
                    *(__half2*)(Col + off) = ll;
                }
            }
        }
    }
}

// ------------------------------------------------------------------
// launch
// ------------------------------------------------------------------
extern "C" void kernel_launch(void* const* d_in, const int* in_sizes, int n_in,
                              void* d_out, int out_size)
{
    const float* queries = (const float*)d_in[0];
    const float* keys    = (const float*)d_in[1];
    const float* values  = (const float*)d_in[2];
    const float* Wq = (const float*)d_in[3];
    const float* bq = (const float*)d_in[4];
    const float* Wk = (const float*)d_in[5];
    const float* bk = (const float*)d_in[6];
    const float* Wv = (const float*)d_in[7];
    const float* bv = (const float*)d_in[8];
    const float* Wg = (const float*)d_in[9];
    const float* bg = (const float*)d_in[10];
    const float* Wo = (const float*)d_in[11];
    const float* bo = (const float*)d_in[12];
    float* out = (float*)d_out;

    fp16 *iqh, *iql, *ikh, *ikl, *ivh, *ivl, *wt;
    fp16 *qh, *ql, *kh, *kl, *vth, *vtl, *ph, *pl, *ch, *cl;
    float *v, *gate, *sc;
    cudaGetSymbolAddress((void**)&iqh, g_iqh); cudaGetSymbolAddress((void**)&iql, g_iql);
    cudaGetSymbolAddress((void**)&ikh, g_ikh); cudaGetSymbolAddress((void**)&ikl, g_ikl);
    cudaGetSymbolAddress((void**)&ivh, g_ivh); cudaGetSymbolAddress((void**)&ivl, g_ivl);
    cudaGetSymbolAddress((void**)&wt,  g_wt);
    cudaGetSymbolAddress((void**)&qh,  g_qh);  cudaGetSymbolAddress((void**)&ql,  g_ql);
    cudaGetSymbolAddress((void**)&kh,  g_kh);  cudaGetSymbolAddress((void**)&kl,  g_kl);
    cudaGetSymbolAddress((void**)&v,   g_v);
    cudaGetSymbolAddress((void**)&vth, g_vth); cudaGetSymbolAddress((void**)&vtl, g_vtl);
    cudaGetSymbolAddress((void**)&gate, g_gate);
    cudaGetSymbolAddress((void**)&sc,  g_sc);
    cudaGetSymbolAddress((void**)&ph,  g_ph);  cudaGetSymbolAddress((void**)&pl,  g_pl);
    cudaGetSymbolAddress((void**)&ch,  g_ch);  cudaGetSymbolAddress((void**)&cl,  g_cl);

    const size_t WSZ = (size_t)DDIM * DDIM;
    fp16* wth[5]; fp16* wtl[5];
    for (int w = 0; w < 5; w++) { wth[w] = wt + (2*w)*WSZ; wtl[w] = wt + (2*w+1)*WSZ; }

    cudaFuncSetAttribute(gemm3, cudaFuncAttributeMaxDynamicSharedMemorySize, GEMM_SMEM);

    const size_t nElem = (size_t)MTOT * DDIM;
    const int splitBlocks = (int)(nElem / 1024);

    // 1. split inputs
    split_f32<<<splitBlocks, 256>>>(queries, iqh, iql, nElem);
    split_f32<<<splitBlocks, 256>>>(keys,    ikh, ikl, nElem);
    split_f32<<<splitBlocks, 256>>>(values,  ivh, ivl, nElem);

    // 2. transpose+split weights: W[K,N] -> Wt[N,K]
    dim3 tb(32, 8);
    transpose_split<<<dim3(32, 32, 1), tb>>>(Wq, wth[0], wtl[0], DDIM, DDIM, 0, 0);
    transpose_split<<<dim3(32, 32, 1), tb>>>(Wk, wth[1], wtl[1], DDIM, DDIM, 0, 0);
    transpose_split<<<dim3(32, 32, 1), tb>>>(Wv, wth[2], wtl[2], DDIM, DDIM, 0, 0);
    transpose_split<<<dim3(32, 32, 1), tb>>>(Wg, wth[3], wtl[3], DDIM, DDIM, 0, 0);
    transpose_split<<<dim3(32, 32, 1), tb>>>(Wo, wth[4], wtl[4], DDIM, DDIM, 0, 0);

    // 3. projections
    dim3 gp(DDIM / 128, MTOT / 128, 1);
    gemm3<<<gp, 256, GEMM_SMEM>>>(iqh, iql, wth[0], wtl[0], 0, 0, DDIM,
                                  nullptr, qh, ql, DDIM, 0, bq, nullptr, 0, 2);
    gemm3<<<gp, 256, GEMM_SMEM>>>(ikh, ikl, wth[1], wtl[1], 0, 0, DDIM,
                                  nullptr, kh, kl, DDIM, 0, bk, nullptr, 0, 2);
    gemm3<<<gp, 256, GEMM_SMEM>>>(ivh, ivl, wth[2], wtl[2], 0, 0, DDIM,
                                  v, nullptr, nullptr, DDIM, 0, bv, nullptr, 0, 1);
    gemm3<<<gp, 256, GEMM_SMEM>>>(iqh, iql, wth[3], wtl[3], 0, 0, DDIM,
                                  gate, nullptr, nullptr, DDIM, 0, bg, nullptr, 0, 3);

    // 4. scores = q @ k^T (per batch)
    gemm3<<<dim3(SEQ / 128, SEQ / 128, BB), 256, GEMM_SMEM>>>(
        qh, ql, kh, kl, (long long)SEQ * DDIM, (long long)SEQ * DDIM, DDIM,
        sc, nullptr, nullptr, SEQ, (long long)SEQ * SEQ, nullptr, nullptr, 0, 0);

    // 5. softmax -> split P
    softmax_split<<<MTOT, 256>>>(sc, ph, pl);

    // 6. transpose+split v per batch: [S,D] -> [D,S]
    transpose_split<<<dim3(DDIM / 32, SEQ / 32, BB), tb>>>(
        v, vth, vtl, SEQ, DDIM, (long long)SEQ * DDIM, (long long)SEQ * DDIM);

    // 7. context = (P @ v) * gate -> split
    gemm3<<<dim3(DDIM / 128, SEQ / 128, BB), 256, GEMM_SMEM>>>(
        ph, pl, vth, vtl, (long long)SEQ * SEQ, (long long)DDIM * SEQ, SEQ,
        nullptr, ch, cl, DDIM, (long long)SEQ * DDIM,
        nullptr, gate, (long long)SEQ * DDIM, 4);

    // 8. out = ctx @ Wo + bo
    gemm3<<<gp, 256, GEMM_SMEM>>>(ch, cl, wth[4], wtl[4], 0, 0, DDIM,
                                  out, nullptr, nullptr, DDIM, 0, bo, nullptr, 0, 1);
}

// round 4
// speedup vs baseline: 3.3473x; 1.1768x over previous
#include <cuda_runtime.h>
#include <cuda_fp16.h>
#include <stdint.h>
#include <math.h>

typedef __half fp16;

#define BB 8
#define SEQ 2048
#define DDIM 1024
#define MTOT (BB * SEQ)   // 16384

// ------------------------------------------------------------------
// PTX helpers (sm_80+ features only)
// ------------------------------------------------------------------
__device__ __forceinline__ uint32_t smem_u32(const void* p) {
    uint32_t a;
    asm("{ .reg .u64 t; cvta.to.shared.u64 t, %1; cvt.u32.u64 %0, t; }"
        : "=r"(a) : "l"(p));
    return a;
}
#define CP16(dst, src) \
    asm volatile("cp.async.cg.shared.global [%0], [%1], 16;" :: "r"(dst), "l"(src))
#define CP_COMMIT() asm volatile("cp.async.commit_group;" ::: "memory")
#define CP_WAIT2()  asm volatile("cp.async.wait_group 2;" ::: "memory")

__device__ __forceinline__ void ldmx4(uint32_t* r, uint32_t addr) {
    asm volatile("ldmatrix.sync.aligned.m8n8.x4.shared.b16 {%0,%1,%2,%3}, [%4];"
        : "=r"(r[0]), "=r"(r[1]), "=r"(r[2]), "=r"(r[3]) : "r"(addr));
}
// non-volatile: pure computation, lets ptxas interleave with ldmatrix
__device__ __forceinline__ void mma16816(float* c, const uint32_t* a, const uint32_t* b) {
    asm("mma.sync.aligned.m16n8k16.row.col.f32.f16.f16.f32 "
        "{%0,%1,%2,%3}, {%4,%5,%6,%7}, {%8,%9}, {%0,%1,%2,%3};"
        : "+f"(c[0]), "+f"(c[1]), "+f"(c[2]), "+f"(c[3])
        : "r"(a[0]), "r"(a[1]), "r"(a[2]), "r"(a[3]), "r"(b[0]), "r"(b[1]));
}

// ------------------------------------------------------------------
// Scratch (static device globals; allocation forbidden)
// ------------------------------------------------------------------
__device__ fp16 g_iqh[(size_t)MTOT * DDIM], g_iql[(size_t)MTOT * DDIM];
__device__ fp16 g_ikh[(size_t)MTOT * DDIM], g_ikl[(size_t)MTOT * DDIM];
__device__ fp16 g_ivh[(size_t)MTOT * DDIM], g_ivl[(size_t)MTOT * DDIM];
__device__ fp16 g_wt[5][2][(size_t)DDIM * DDIM];
__device__ fp16 g_qh[(size_t)MTOT * DDIM], g_ql[(size_t)MTOT * DDIM];
__device__ fp16 g_kh[(size_t)MTOT * DDIM], g_kl[(size_t)MTOT * DDIM];
__device__ float g_v[(size_t)MTOT * DDIM];
__device__ fp16 g_vth[(size_t)BB * DDIM * SEQ], g_vtl[(size_t)BB * DDIM * SEQ];
__device__ float g_gate[(size_t)MTOT * DDIM];
__device__ float g_sc[(size_t)BB * SEQ * SEQ];
__device__ fp16 g_ph[(size_t)BB * SEQ * SEQ];
__device__ fp16 g_ch[(size_t)MTOT * DDIM], g_cl[(size_t)MTOT * DDIM];

// ------------------------------------------------------------------
// Elementwise split: fp32 -> hi(fp16), lo(fp16)
// ------------------------------------------------------------------
__global__ __launch_bounds__(256)
void split_f32(const float* __restrict__ x, fp16* __restrict__ h,
               fp16* __restrict__ l, size_t n)
{
    size_t i = ((size_t)blockIdx.x * 256 + threadIdx.x) * 4;
    if (i >= n) return;
    float4 v = *(const float4*)(x + i);
    fp16 h0 = __float2half(v.x), h1 = __float2half(v.y);
    fp16 h2 = __float2half(v.z), h3 = __float2half(v.w);
    __half2 hh0, hh1, ll0, ll1;
    hh0.x = h0; hh0.y = h1; hh1.x = h2; hh1.y = h3;
    ll0.x = __float2half(v.x - __half2float(h0));
    ll0.y = __float2half(v.y - __half2float(h1));
    ll1.x = __float2half(v.z - __half2float(h2));
    ll1.y = __float2half(v.w - __half2float(h3));
    *(__half2*)(h + i)     = hh0;
    *(__half2*)(h + i + 2) = hh1;
    *(__half2*)(l + i)     = ll0;
    *(__half2*)(l + i + 2) = ll1;
}

// ------------------------------------------------------------------
// Transpose + split: src [R,C] fp32 -> dst [C,R] hi/lo fp16 (batched)
// ------------------------------------------------------------------
__global__ __launch_bounds__(256)
void transpose_split(const float* __restrict__ src, fp16* __restrict__ dh,
                     fp16* __restrict__ dl, int R, int C,
                     long long sb, long long db)
{
    __shared__ float t[32][33];
    src += (long long)blockIdx.z * sb;
    dh  += (long long)blockIdx.z * db;
    dl  += (long long)blockIdx.z * db;
    int r0 = blockIdx.y * 32, c0 = blockIdx.x * 32;
#pragma unroll
    for (int i = 0; i < 32; i += 8)
        t[threadIdx.y + i][threadIdx.x] =
            src[(size_t)(r0 + threadIdx.y + i) * C + c0 + threadIdx.x];
    __syncthreads();
#pragma unroll
    for (int i = 0; i < 32; i += 8) {
        int cc = c0 + threadIdx.y + i;
        int rr = r0 + threadIdx.x;
        float v = t[threadIdx.x][threadIdx.y + i];
        fp16 h = __float2half(v);
        dh[(size_t)cc * R + rr] = h;
        dl[(size_t)cc * R + rr] = __float2half(v - __half2float(h));
    }
}

// ------------------------------------------------------------------
// Row softmax: fp32 scores -> fp16 P (hi only; P error absorbed by budget)
// ------------------------------------------------------------------
__global__ __launch_bounds__(256)
void softmax_p(const float* __restrict__ Sc, fp16* __restrict__ Ph)
{
    __shared__ float red[256];
    const size_t row = blockIdx.x;
    const int tid = threadIdx.x;
    const float* p = Sc + row * SEQ;

    float m = -INFINITY;
    for (int j = tid; j < SEQ; j += 256) m = fmaxf(m, p[j]);
    red[tid] = m; __syncthreads();
    for (int s = 128; s > 0; s >>= 1) {
        if (tid < s) red[tid] = fmaxf(red[tid], red[tid + s]);
        __syncthreads();
    }
    m = red[0]; __syncthreads();

    float sum = 0.0f;
    for (int j = tid; j < SEQ; j += 256) sum += __expf(p[j] - m);
    red[tid] = sum; __syncthreads();
    for (int s = 128; s > 0; s >>= 1) {
        if (tid < s) red[tid] += red[tid + s];
        __syncthreads();
    }
    float inv = 1.0f / red[0];

    for (int j = tid; j < SEQ; j += 256)
        Ph[row * SEQ + j] = __float2half(__expf(p[j] - m) * inv);
}

// ------------------------------------------------------------------
// mma.sync fp16 split-emulated GEMM: C[M,N] = A[M,K] @ B[N,K]^T
// mode 0: 3-pass  A{hi,lo,hi} B{hi,hi,lo}   (full 3-term emulation)
// mode 1: 2-pass  A{hi,lo}    B{hi,hi}      (keep A residual)
// mode 2: 2-pass  A{hi,hi}    B{hi,lo}      (keep B residual)
// epi: 0=fp32, 1=bias fp32, 2=bias+split, 3=bias+sigmoid fp32, 4=gate*split
// ------------------------------------------------------------------
#define STAGES 3
#define STAGE_BYTES 32768
#define GEMM_SMEM (STAGES * STAGE_BYTES)

__global__ __launch_bounds__(256, 2)
void gemm3(const fp16* __restrict__ Ah, const fp16* __restrict__ Al,
           const fp16* __restrict__ Bh, const fp16* __restrict__ Bl,
           long long sAb, long long sBb, int K, int mode,
           float* __restrict__ Cf, fp16* __restrict__ Coh, fp16* __restrict__ Col,
           int ldc, long long sCb,
           const float* __restrict__ bias, const float* __restrict__ gate,
           long long sGb, int epi)
{
    extern __shared__ char dsm[];
    const uint32_t sbase = smem_u32(dsm);

    const int tid  = threadIdx.x;
    const int wid  = tid >> 5;
    const int lane = tid & 31;
    const int wm = wid >> 1;          // 0..3
    const int wn = wid & 1;           // 0..1
    const int z  = blockIdx.z;
    Ah += (long long)z * sAb; Al += (long long)z * sAb;
    Bh += (long long)z * sBb; Bl += (long long)z * sBb;

    const int m0 = blockIdx.y * 128;
    const int n0 = blockIdx.x * 128;
    const int KC = K >> 6;
    const int npass = (mode == 0) ? 3 : 2;
    const int NC = npass * KC;

    int rows[4], cols[4];
    uint32_t soff[4];
#pragma unroll
    for (int i = 0; i < 4; i++) {
        int idx = tid + i * 256;
        rows[i] = idx >> 3;
        cols[i] = idx & 7;
        soff[i] = (uint32_t)(rows[i] * 128 + ((cols[i] ^ (rows[i] & 7)) << 4));
    }

    auto load_chunk = [&](int c, int stage) {
        int phase = c / KC;
        int inner = c - phase * KC;
        const fp16* As = Ah;
        const fp16* Bs = Bh;
        if (mode == 0) {
            if (phase == 1) As = Al;
            if (phase == 2) Bs = Bl;
        } else if (mode == 1) {
            if (phase == 1) As = Al;
        } else {
            if (phase == 1) Bs = Bl;
        }
        uint32_t aB = sbase + (uint32_t)stage * STAGE_BYTES;
        uint32_t bB = aB + 16384u;
#pragma unroll
        for (int i = 0; i < 4; i++)
            CP16(aB + soff[i], As + (size_t)(m0 + rows[i]) * K + inner * 64 + cols[i] * 8);
#pragma unroll
        for (int i = 0; i < 4; i++)
            CP16(bB + soff[i], Bs + (size_t)(n0 + rows[i]) * K + inner * 64 + cols[i] * 8);
    };

    for (int s = 0; s < STAGES; s++) { load_chunk(s, s); CP_COMMIT(); }

    float acc[2][8][4];
#pragma unroll
    for (int mt = 0; mt < 2; mt++)
#pragma unroll
        for (int nt = 0; nt < 8; nt++)
#pragma unroll
            for (int r = 0; r < 4; r++) acc[mt][nt][r] = 0.0f;

    const int aRowBase = wm * 32 + (lane & 15);
    const int bRowBase = wn * 64 + (lane & 15);
    const int khalf    = lane >> 4;

    for (int c = 0; c < NC; c++) {
        const int st = c % STAGES;
        CP_WAIT2();
        __syncthreads();
        const uint32_t aB = sbase + (uint32_t)st * STAGE_BYTES;
        const uint32_t bB = aB + 16384u;
#pragma unroll
        for (int ks = 0; ks < 4; ks++) {
            const int ch = 2 * ks + khalf;
            uint32_t afr[2][4];
#pragma unroll
            for (int mt = 0; mt < 2; mt++) {
                int r = aRowBase + mt * 16;
                ldmx4(afr[mt], aB + (uint32_t)(r * 128 + ((ch ^ (r & 7)) << 4)));
            }
            uint32_t bfr[8][2];
#pragma unroll
            for (int nb = 0; nb < 4; nb++) {
                int r = bRowBase + nb * 16;
                uint32_t t4[4];
                ldmx4(t4, bB + (uint32_t)(r * 128 + ((ch ^ (r & 7)) << 4)));
                bfr[nb * 2][0]     = t4[0];
                bfr[nb * 2][1]     = t4[2];
                bfr[nb * 2 + 1][0] = t4[1];
                bfr[nb * 2 + 1][1] = t4[3];
            }
#pragma unroll
            for (int mt = 0; mt < 2; mt++)
#pragma unroll
                for (int nt = 0; nt < 8; nt++)
                    mma16816(acc[mt][nt], afr[mt], bfr[nt]);
        }
        __syncthreads();
        if (c + STAGES < NC) load_chunk(c + STAGES, st);
        CP_COMMIT();
    }

    // ---------------- epilogue ----------------
    const int erow0 = m0 + wm * 32 + (lane >> 2);
    const int ecol0 = n0 + wn * 64 + (lane & 3) * 2;

#pragma unroll
    for (int mt = 0; mt < 2; mt++) {
#pragma unroll
        for (int rr = 0; rr < 2; rr++) {
            const int row = erow0 + mt * 16 + rr * 8;
#pragma unroll
            for (int nt = 0; nt < 8; nt++) {
                const int col = ecol0 + nt * 8;
                float v0 = acc[mt][nt][2 * rr];
                float v1 = acc[mt][nt][2 * rr + 1];
                const size_t off = (size_t)z * sCb + (size_t)row * ldc + col;
                if (epi == 0) {
                    *(float2*)(Cf + off) = make_float2(v0, v1);
                } else if (epi == 1 || epi == 3) {
                    v0 += bias[col]; v1 += bias[col + 1];
                    if (epi == 3) {
                        v0 = 1.0f / (1.0f + __expf(-v0));
                        v1 = 1.0f / (1.0f + __expf(-v1));
                    }
                    *(float2*)(Cf + off) = make_float2(v0, v1);
                } else {
                    if (epi == 2) {
                        v0 += bias[col]; v1 += bias[col + 1];
                    } else {
                        float2 gg = *(const float2*)(gate + (size_t)z * sGb +
                                                     (size_t)row * ldc + col);
                        v0 *= gg.x; v1 *= gg.y;
                    }
                    fp16 h0 = __float2half(v0), h1 = __float2half(v1);
                    __half2 hh, ll;
                    hh.x = h0; hh.y = h1;
                    ll.x = __float2half(v0 - __half2float(h0));
                    ll.y = __float2half(v1 - __half2float(h1));
                    *(__half2*)(Coh + off) = hh;
                    *(__half2*)(Col + off) = ll;
                }
            }
        }
    }
}

// ------------------------------------------------------------------
// launch
// ------------------------------------------------------------------
extern "C" void kernel_launch(void* const* d_in, const int* in_sizes, int n_in,
                              void* d_out, int out_size)
{
    const float* queries = (const float*)d_in[0];
    const float* keys    = (const float*)d_in[1];
    const float* values  = (const float*)d_in[2];
    const float* Wq = (const float*)d_in[3];
    const float* bq = (const float*)d_in[4];
    const float* Wk = (const float*)d_in[5];
    const float* bk = (const float*)d_in[6];
    const float* Wv = (const float*)d_in[7];
    const float* bv = (const float*)d_in[8];
    const float* Wg = (const float*)d_in[9];
    const float* bg = (const float*)d_in[10];
    const float* Wo = (const float*)d_in[11];
    const float* bo = (const float*)d_in[12];
    float* out = (float*)d_out;

    fp16 *iqh, *iql, *ikh, *ikl, *ivh, *ivl, *wt;
    fp16 *qh, *ql, *kh, *kl, *vth, *vtl, *ph, *ch, *cl;
    float *v, *gate, *sc;
    cudaGetSymbolAddress((void**)&iqh, g_iqh); cudaGetSymbolAddress((void**)&iql, g_iql);
    cudaGetSymbolAddress((void**)&ikh, g_ikh); cudaGetSymbolAddress((void**)&ikl, g_ikl);
    cudaGetSymbolAddress((void**)&ivh, g_ivh); cudaGetSymbolAddress((void**)&ivl, g_ivl);
    cudaGetSymbolAddress((void**)&wt,  g_wt);
    cudaGetSymbolAddress((void**)&qh,  g_qh);  cudaGetSymbolAddress((void**)&ql,  g_ql);
    cudaGetSymbolAddress((void**)&kh,  g_kh);  cudaGetSymbolAddress((void**)&kl,  g_kl);
    cudaGetSymbolAddress((void**)&v,   g_v);
    cudaGetSymbolAddress((void**)&vth, g_vth); cudaGetSymbolAddress((void**)&vtl, g_vtl);
    cudaGetSymbolAddress((void**)&gate, g_gate);
    cudaGetSymbolAddress((void**)&sc,  g_sc);
    cudaGetSymbolAddress((void**)&ph,  g_ph);
    cudaGetSymbolAddress((void**)&ch,  g_ch);  cudaGetSymbolAddress((void**)&cl,  g_cl);

    const size_t WSZ = (size_t)DDIM * DDIM;
    fp16* wth[5]; fp16* wtl[5];
    for (int w = 0; w < 5; w++) { wth[w] = wt + (2*w)*WSZ; wtl[w] = wt + (2*w+1)*WSZ; }

    cudaFuncSetAttribute(gemm3, cudaFuncAttributeMaxDynamicSharedMemorySize, GEMM_SMEM);

    const size_t nElem = (size_t)MTOT * DDIM;
    const int splitBlocks = (int)(nElem / 1024);

    // 1. split inputs
    split_f32<<<splitBlocks, 256>>>(queries, iqh, iql, nElem);
    split_f32<<<splitBlocks, 256>>>(keys,    ikh, ikl, nElem);
    split_f32<<<splitBlocks, 256>>>(values,  ivh, ivl, nElem);

    // 2. transpose+split weights: W[K,N] -> Wt[N,K]
    dim3 tb(32, 8);
    transpose_split<<<dim3(32, 32, 1), tb>>>(Wq, wth[0], wtl[0], DDIM, DDIM, 0, 0);
    transpose_split<<<dim3(32, 32, 1), tb>>>(Wk, wth[1], wtl[1], DDIM, DDIM, 0, 0);
    transpose_split<<<dim3(32, 32, 1), tb>>>(Wv, wth[2], wtl[2], DDIM, DDIM, 0, 0);
    transpose_split<<<dim3(32, 32, 1), tb>>>(Wg, wth[3], wtl[3], DDIM, DDIM, 0, 0);
    transpose_split<<<dim3(32, 32, 1), tb>>>(Wo, wth[4], wtl[4], DDIM, DDIM, 0, 0);

    // 3. projections
    dim3 gp(DDIM / 128, MTOT / 128, 1);
    // q, k: full 3-pass (feed the softmax logits; x32 error amplification)
    gemm3<<<gp, 256, GEMM_SMEM>>>(iqh, iql, wth[0], wtl[0], 0, 0, DDIM, 0,
                                  nullptr, qh, ql, DDIM, 0, bq, nullptr, 0, 2);
    gemm3<<<gp, 256, GEMM_SMEM>>>(ikh, ikl, wth[1], wtl[1], 0, 0, DDIM, 0,
                                  nullptr, kh, kl, DDIM, 0, bk, nullptr, 0, 2);
    // v, gate: 2-pass (A-residual kept, weight residual dropped)
    gemm3<<<gp, 256, GEMM_SMEM>>>(ivh, ivl, wth[2], wtl[2], 0, 0, DDIM, 1,
                                  v, nullptr, nullptr, DDIM, 0, bv, nullptr, 0, 1);
    gemm3<<<gp, 256, GEMM_SMEM>>>(iqh, iql, wth[3], wtl[3], 0, 0, DDIM, 1,
                                  gate, nullptr, nullptr, DDIM, 0, bg, nullptr, 0, 3);

    // 4. scores = q @ k^T (per batch), full 3-pass
    gemm3<<<dim3(SEQ / 128, SEQ / 128, BB), 256, GEMM_SMEM>>>(
        qh, ql, kh, kl, (long long)SEQ * DDIM, (long long)SEQ * DDIM, DDIM, 0,
        sc, nullptr, nullptr, SEQ, (long long)SEQ * SEQ, nullptr, nullptr, 0, 0);

    // 5. softmax -> fp16 P (hi only)
    softmax_p<<<MTOT, 256>>>(sc, ph);

    // 6. transpose+split v per batch: [S,D] -> [D,S]
    transpose_split<<<dim3(DDIM / 32, SEQ / 32, BB), tb>>>(
        v, vth, vtl, SEQ, DDIM, (long long)SEQ * DDIM, (long long)SEQ * DDIM);

    // 7. context = (P @ v) * gate -> split; 2-pass, B-residual (P single)
    gemm3<<<dim3(DDIM / 128, SEQ / 128, BB), 256, GEMM_SMEM>>>(
        ph, ph, vth, vtl, (long long)SEQ * SEQ, (long long)DDIM * SEQ, SEQ, 2,
        nullptr, ch, cl, DDIM, (long long)SEQ * DDIM,
        nullptr, gate, (long long)SEQ * DDIM, 4);

    // 8. out = ctx @ Wo + bo; 2-pass, A-residual (ctx split)
    gemm3<<<gp, 256, GEMM_SMEM>>>(ch, cl, wth[4], wtl[4], 0, 0, DDIM, 1,
                                  out, nullptr, nullptr, DDIM, 0, bo, nullptr, 0, 1);
}

// round 5
// speedup vs baseline: 3.6644x; 1.0948x over previous
#include <cuda_runtime.h>
#include <cuda_fp16.h>
#include <stdint.h>
#include <math.h>

typedef __half fp16;

#define BB 8
#define SEQ 2048
#define DDIM 1024
#define MTOT (BB * SEQ)   // 16384

// ------------------------------------------------------------------
// PTX helpers (sm_80+ features only)
// ------------------------------------------------------------------
__device__ __forceinline__ uint32_t smem_u32(const void* p) {
    uint32_t a;
    asm("{ .reg .u64 t; cvta.to.shared.u64 t, %1; cvt.u32.u64 %0, t; }"
        : "=r"(a) : "l"(p));
    return a;
}
#define CP16(dst, src) \
    asm volatile("cp.async.cg.shared.global [%0], [%1], 16;" :: "r"(dst), "l"(src))
#define CP_COMMIT() asm volatile("cp.async.commit_group;" ::: "memory")
#define CP_WAIT1()  asm volatile("cp.async.wait_group 1;" ::: "memory")

__device__ __forceinline__ void ldmx4(uint32_t* r, uint32_t addr) {
    asm volatile("ldmatrix.sync.aligned.m8n8.x4.shared.b16 {%0,%1,%2,%3}, [%4];"
        : "=r"(r[0]), "=r"(r[1]), "=r"(r[2]), "=r"(r[3]) : "r"(addr));
}
__device__ __forceinline__ void mma16816(float* c, const uint32_t* a, const uint32_t* b) {
    asm("mma.sync.aligned.m16n8k16.row.col.f32.f16.f16.f32 "
        "{%0,%1,%2,%3}, {%4,%5,%6,%7}, {%8,%9}, {%0,%1,%2,%3};"
        : "+f"(c[0]), "+f"(c[1]), "+f"(c[2]), "+f"(c[3])
        : "r"(a[0]), "r"(a[1]), "r"(a[2]), "r"(a[3]), "r"(b[0]), "r"(b[1]));
}

// ------------------------------------------------------------------
// Scratch (static device globals; allocation forbidden)
// ------------------------------------------------------------------
__device__ fp16 g_iqh[(size_t)MTOT * DDIM], g_iql[(size_t)MTOT * DDIM];
__device__ fp16 g_ikh[(size_t)MTOT * DDIM], g_ikl[(size_t)MTOT * DDIM];
__device__ fp16 g_ivh[(size_t)MTOT * DDIM], g_ivl[(size_t)MTOT * DDIM];
__device__ fp16 g_wt[5][2][(size_t)DDIM * DDIM];
__device__ fp16 g_qh[(size_t)MTOT * DDIM], g_ql[(size_t)MTOT * DDIM];
__device__ fp16 g_kh[(size_t)MTOT * DDIM], g_kl[(size_t)MTOT * DDIM];
__device__ float g_v[(size_t)MTOT * DDIM];
__device__ fp16 g_vth[(size_t)BB * DDIM * SEQ], g_vtl[(size_t)BB * DDIM * SEQ];
__device__ float g_gate[(size_t)MTOT * DDIM];
__device__ float g_sc[(size_t)BB * SEQ * SEQ];
__device__ fp16 g_ph[(size_t)BB * SEQ * SEQ];
__device__ fp16 g_ch[(size_t)MTOT * DDIM], g_cl[(size_t)MTOT * DDIM];

// ------------------------------------------------------------------
// Elementwise split: fp32 -> hi(fp16), lo(fp16)
// ------------------------------------------------------------------
__global__ __launch_bounds__(256)
void split_f32(const float* __restrict__ x, fp16* __restrict__ h,
               fp16* __restrict__ l, size_t n)
{
    size_t i = ((size_t)blockIdx.x * 256 + threadIdx.x) * 4;
    if (i >= n) return;
    float4 v = *(const float4*)(x + i);
    fp16 h0 = __float2half(v.x), h1 = __float2half(v.y);
    fp16 h2 = __float2half(v.z), h3 = __float2half(v.w);
    __half2 hh0, hh1, ll0, ll1;
    hh0.x = h0; hh0.y = h1; hh1.x = h2; hh1.y = h3;
    ll0.x = __float2half(v.x - __half2float(h0));
    ll0.y = __float2half(v.y - __half2float(h1));
    ll1.x = __float2half(v.z - __half2float(h2));
    ll1.y = __float2half(v.w - __half2float(h3));
    *(__half2*)(h + i)     = hh0;
    *(__half2*)(h + i + 2) = hh1;
    *(__half2*)(l + i)     = ll0;
    *(__half2*)(l + i + 2) = ll1;
}

// ------------------------------------------------------------------
// Transpose + split: src [R,C] fp32 -> dst [C,R] hi/lo fp16 (batched)
// ------------------------------------------------------------------
__global__ __launch_bounds__(256)
void transpose_split(const float* __restrict__ src, fp16* __restrict__ dh,
                     fp16* __restrict__ dl, int R, int C,
                     long long sb, long long db)
{
    __shared__ float t[32][33];
    src += (long long)blockIdx.z * sb;
    dh  += (long long)blockIdx.z * db;
    dl  += (long long)blockIdx.z * db;
    int r0 = blockIdx.y * 32, c0 = blockIdx.x * 32;
#pragma unroll
    for (int i = 0; i < 32; i += 8)
        t[threadIdx.y + i][threadIdx.x] =
            src[(size_t)(r0 + threadIdx.y + i) * C + c0 + threadIdx.x];
    __syncthreads();
#pragma unroll
    for (int i = 0; i < 32; i += 8) {
        int cc = c0 + threadIdx.y + i;
        int rr = r0 + threadIdx.x;
        float v = t[threadIdx.x][threadIdx.y + i];
        fp16 h = __float2half(v);
        dh[(size_t)cc * R + rr] = h;
        dl[(size_t)cc * R + rr] = __float2half(v - __half2float(h));
    }
}

// ------------------------------------------------------------------
// Register-resident row softmax: one read + one fp16 write.
// 2048 cols / 256 threads = 8 floats per thread.
// ------------------------------------------------------------------
__global__ __launch_bounds__(256)
void softmax_p(const float* __restrict__ Sc, fp16* __restrict__ Ph)
{
    __shared__ float red[8];
    const size_t row = blockIdx.x;
    const int tid  = threadIdx.x;
    const int lane = tid & 31;
    const int wrp  = tid >> 5;
    const float* p = Sc + row * SEQ;

    float r[8];
#pragma unroll
    for (int i = 0; i < 8; i++) r[i] = p[tid + i * 256];

    float m = r[0];
#pragma unroll
    for (int i = 1; i < 8; i++) m = fmaxf(m, r[i]);
#pragma unroll
    for (int o = 16; o > 0; o >>= 1)
        m = fmaxf(m, __shfl_xor_sync(0xFFFFFFFFu, m, o));
    if (lane == 0) red[wrp] = m;
    __syncthreads();
    float gm = red[0];
#pragma unroll
    for (int j = 1; j < 8; j++) gm = fmaxf(gm, red[j]);
    __syncthreads();

    float s = 0.0f;
#pragma unroll
    for (int i = 0; i < 8; i++) { r[i] = __expf(r[i] - gm); s += r[i]; }
#pragma unroll
    for (int o = 16; o > 0; o >>= 1)
        s += __shfl_xor_sync(0xFFFFFFFFu, s, o);
    if (lane == 0) red[wrp] = s;
    __syncthreads();
    float gs = red[0];
#pragma unroll
    for (int j = 1; j < 8; j++) gs += red[j];
    float inv = 1.0f / gs;

#pragma unroll
    for (int i = 0; i < 8; i++)
        Ph[row * SEQ + tid + i * 256] = __float2half(r[i] * inv);
}

// ------------------------------------------------------------------
// mma.sync fp16 split-emulated GEMM: C[M,N] = A[M,K] @ B[N,K]^T
// mode 0: 3-pass A{hi,lo,hi} B{hi,hi,lo}
// mode 1: 2-pass A{hi,lo}    B{hi,hi}
// mode 2: 2-pass A{hi,hi}    B{hi,lo}
// mode 3: 1-pass A{hi}       B{hi}
// epi: 0=fp32, 1=bias fp32, 2=bias+split, 3=bias+sigmoid fp32, 4=gate*split
// Single __syncthreads per K-chunk (CUTLASS-style multistage).
// ------------------------------------------------------------------
#define STAGES 3
#define STAGE_BYTES 32768
#define GEMM_SMEM (STAGES * STAGE_BYTES)

__global__ __launch_bounds__(256, 2)
void gemm3(const fp16* __restrict__ Ah, const fp16* __restrict__ Al,
           const fp16* __restrict__ Bh, const fp16* __restrict__ Bl,
           long long sAb, long long sBb, int K, int mode,
           float* __restrict__ Cf, fp16* __restrict__ Coh, fp16* __restrict__ Col,
           int ldc, long long sCb,
           const float* __restrict__ bias, const float* __restrict__ gate,
           long long sGb, int epi)
{
    extern __shared__ char dsm[];
    const uint32_t sbase = smem_u32(dsm);

    const int tid  = threadIdx.x;
    const int wid  = tid >> 5;
    const int lane = tid & 31;
    const int wm = wid >> 1;          // 0..3
    const int wn = wid & 1;           // 0..1
    const int z  = blockIdx.z;
    Ah += (long long)z * sAb; Al += (long long)z * sAb;
    Bh += (long long)z * sBb; Bl += (long long)z * sBb;

    const int m0 = blockIdx.y * 128;
    const int n0 = blockIdx.x * 128;
    const int KC = K >> 6;
    const int npass = (mode == 0) ? 3 : ((mode == 3) ? 1 : 2);
    const int NC = npass * KC;

    int rows[4], cols[4];
    uint32_t soff[4];
#pragma unroll
    for (int i = 0; i < 4; i++) {
        int idx = tid + i * 256;
        rows[i] = idx >> 3;
        cols[i] = idx & 7;
        soff[i] = (uint32_t)(rows[i] * 128 + ((cols[i] ^ (rows[i] & 7)) << 4));
    }

    auto load_chunk = [&](int c, int stage) {
        int phase = c / KC;
        int inner = c - phase * KC;
        const fp16* As = Ah;
        const fp16* Bs = Bh;
        if (mode == 0) {
            if (phase == 1) As = Al;
            if (phase == 2) Bs = Bl;
        } else if (mode == 1) {
            if (phase == 1) As = Al;
        } else if (mode == 2) {
            if (phase == 1) Bs = Bl;
        }
        uint32_t aB = sbase + (uint32_t)stage * STAGE_BYTES;
        uint32_t bB = aB + 16384u;
#pragma unroll
        for (int i = 0; i < 4; i++)
            CP16(aB + soff[i], As + (size_t)(m0 + rows[i]) * K + inner * 64 + cols[i] * 8);
#pragma unroll
        for (int i = 0; i < 4; i++)
            CP16(bB + soff[i], Bs + (size_t)(n0 + rows[i]) * K + inner * 64 + cols[i] * 8);
    };

    // prologue: stages 0 and 1 in flight (2 groups)
    load_chunk(0, 0); CP_COMMIT();
    load_chunk(1, 1); CP_COMMIT();

    float acc[2][8][4];
#pragma unroll
    for (int mt = 0; mt < 2; mt++)
#pragma unroll
        for (int nt = 0; nt < 8; nt++)
#pragma unroll
            for (int r = 0; r < 4; r++) acc[mt][nt][r] = 0.0f;

    const int aRowBase = wm * 32 + (lane & 15);
    const int bRowBase = wn * 64 + (lane & 15);
    const int khalf    = lane >> 4;

    for (int c = 0; c < NC; c++) {
        const int st = c % STAGES;
        CP_WAIT1();            // chunk c complete (c+1's group is the newest)
        __syncthreads();       // data visible; stage (c-1)%S free for rewrite
        if (c + 2 < NC) load_chunk(c + 2, (c + 2) % STAGES);
        CP_COMMIT();           // real or empty — keeps group accounting exact
        const uint32_t aB = sbase + (uint32_t)st * STAGE_BYTES;
        const uint32_t bB = aB + 16384u;
#pragma unroll
        for (int ks = 0; ks < 4; ks++) {
            const int ch = 2 * ks + khalf;
            uint32_t afr[2][4];
#pragma unroll
            for (int mt = 0; mt < 2; mt++) {
                int r = aRowBase + mt * 16;
                ldmx4(afr[mt], aB + (uint32_t)(r * 128 + ((ch ^ (r & 7)) << 4)));
            }
            uint32_t bfr[8][2];
#pragma unroll
            for (int nb = 0; nb < 4; nb++) {
                int r = bRowBase + nb * 16;
                uint32_t t4[4];
                ldmx4(t4, bB + (uint32_t)(r * 128 + ((ch ^ (r & 7)) << 4)));
                bfr[nb * 2][0]     = t4[0];
                bfr[nb * 2][1]     = t4[2];
                bfr[nb * 2 + 1][0] = t4[1];
                bfr[nb * 2 + 1][1] = t4[3];
            }
#pragma unroll
            for (int mt = 0; mt < 2; mt++)
#pragma unroll
                for (int nt = 0; nt < 8; nt++)
                    mma16816(acc[mt][nt], afr[mt], bfr[nt]);
        }
    }

    // ---------------- epilogue ----------------
    const int erow0 = m0 + wm * 32 + (lane >> 2);
    const int ecol0 = n0 + wn * 64 + (lane & 3) * 2;

#pragma unroll
    for (int mt = 0; mt < 2; mt++) {
#pragma unroll
        for (int rr = 0; rr < 2; rr++) {
            const int row = erow0 + mt * 16 + rr * 8;
#pragma unroll
            for (int nt = 0; nt < 8; nt++) {
                const int col = ecol0 + nt * 8;
                float v0 = acc[mt][nt][2 * rr];
                float v1 = acc[mt][nt][2 * rr + 1];
                const size_t off = (size_t)z * sCb + (size_t)row * ldc + col;
                if (epi == 0) {
                    *(float2*)(Cf + off) = make_float2(v0, v1);
                } else if (epi == 1 || epi == 3) {
                    v0 += bias[col]; v1 += bias[col + 1];
                    if (epi == 3) {
                        v0 = 1.0f / (1.0f + __expf(-v0));
                        v1 = 1.0f / (1.0f + __expf(-v1));
                    }
                    *(float2*)(Cf + off) = make_float2(v0, v1);
                } else {
                    if (epi == 2) {
                        v0 += bias[col]; v1 += bias[col + 1];
                    } else {
                        float2 gg = *(const float2*)(gate + (size_t)z * sGb +
                                                     (size_t)row * ldc + col);
                        v0 *= gg.x; v1 *= gg.y;
                    }
                    fp16 h0 = __float2half(v0), h1 = __float2half(v1);
                    __half2 hh, ll;
                    hh.x = h0; hh.y = h1;
                    ll.x = __float2half(v0 - __half2float(h0));
                    ll.y = __float2half(v1 - __half2float(h1));
                    *(__half2*)(Coh + off) = hh;
                    *(__half2*)(Col + off) = ll;
                }
            }
        }
    }
}

// ------------------------------------------------------------------
// launch
// ------------------------------------------------------------------
extern "C" void kernel_launch(void* const* d_in, const int* in_sizes, int n_in,
                              void* d_out, int out_size)
{
    const float* queries = (const float*)d_in[0];
    const float* keys    = (const float*)d_in[1];
    const float* values  = (const float*)d_in[2];
    const float* Wq = (const float*)d_in[3];
    const float* bq = (const float*)d_in[4];
    const float* Wk = (const float*)d_in[5];
    const float* bk = (const float*)d_in[6];
    const float* Wv = (const float*)d_in[7];
    const float* bv = (const float*)d_in[8];
    const float* Wg = (const float*)d_in[9];
    const float* bg = (const float*)d_in[10];
    const float* Wo = (const float*)d_in[11];
    const float* bo = (const float*)d_in[12];
    float* out = (float*)d_out;

    fp16 *iqh, *iql, *ikh, *ikl, *ivh, *ivl, *wt;
    fp16 *qh, *ql, *kh, *kl, *vth, *vtl, *ph, *ch, *cl;
    float *v, *gate, *sc;
    cudaGetSymbolAddress((void**)&iqh, g_iqh); cudaGetSymbolAddress((void**)&iql, g_iql);
    cudaGetSymbolAddress((void**)&ikh, g_ikh); cudaGetSymbolAddress((void**)&ikl, g_ikl);
    cudaGetSymbolAddress((void**)&ivh, g_ivh); cudaGetSymbolAddress((void**)&ivl, g_ivl);
    cudaGetSymbolAddress((void**)&wt,  g_wt);
    cudaGetSymbolAddress((void**)&qh,  g_qh);  cudaGetSymbolAddress((void**)&ql,  g_ql);
    cudaGetSymbolAddress((void**)&kh,  g_kh);  cudaGetSymbolAddress((void**)&kl,  g_kl);
    cudaGetSymbolAddress((void**)&v,   g_v);
    cudaGetSymbolAddress((void**)&vth, g_vth); cudaGetSymbolAddress((void**)&vtl, g_vtl);
    cudaGetSymbolAddress((void**)&gate, g_gate);
    cudaGetSymbolAddress((void**)&sc,  g_sc);
    cudaGetSymbolAddress((void**)&ph,  g_ph);
    cudaGetSymbolAddress((void**)&ch,  g_ch);  cudaGetSymbolAddress((void**)&cl,  g_cl);

    const size_t WSZ = (size_t)DDIM * DDIM;
    fp16* wth[5]; fp16* wtl[5];
    for (int w = 0; w < 5; w++) { wth[w] = wt + (2*w)*WSZ; wtl[w] = wt + (2*w+1)*WSZ; }

    cudaFuncSetAttribute(gemm3, cudaFuncAttributeMaxDynamicSharedMemorySize, GEMM_SMEM);

    const size_t nElem = (size_t)MTOT * DDIM;
    const int splitBlocks = (int)(nElem / 1024);

    // 1. split inputs
    split_f32<<<splitBlocks, 256>>>(queries, iqh, iql, nElem);
    split_f32<<<splitBlocks, 256>>>(keys,    ikh, ikl, nElem);
    split_f32<<<splitBlocks, 256>>>(values,  ivh, ivl, nElem);

    // 2. transpose+split weights: W[K,N] -> Wt[N,K]
    dim3 tb(32, 8);
    transpose_split<<<dim3(32, 32, 1), tb>>>(Wq, wth[0], wtl[0], DDIM, DDIM, 0, 0);
    transpose_split<<<dim3(32, 32, 1), tb>>>(Wk, wth[1], wtl[1], DDIM, DDIM, 0, 0);
    transpose_split<<<dim3(32, 32, 1), tb>>>(Wv, wth[2], wtl[2], DDIM, DDIM, 0, 0);
    transpose_split<<<dim3(32, 32, 1), tb>>>(Wg, wth[3], wtl[3], DDIM, DDIM, 0, 0);
    transpose_split<<<dim3(32, 32, 1), tb>>>(Wo, wth[4], wtl[4], DDIM, DDIM, 0, 0);

    // 3. projections
    dim3 gp(DDIM / 128, MTOT / 128, 1);
    // q, k: full 3-pass (feed softmax logits; x32 error amplification)
    gemm3<<<gp, 256, GEMM_SMEM>>>(iqh, iql, wth[0], wtl[0], 0, 0, DDIM, 0,
                                  nullptr, qh, ql, DDIM, 0, bq, nullptr, 0, 2);
    gemm3<<<gp, 256, GEMM_SMEM>>>(ikh, ikl, wth[1], wtl[1], 0, 0, DDIM, 0,
                                  nullptr, kh, kl, DDIM, 0, bk, nullptr, 0, 2);
    // v: 2-pass (A-residual kept)
    gemm3<<<gp, 256, GEMM_SMEM>>>(ivh, ivl, wth[2], wtl[2], 0, 0, DDIM, 1,
                                  v, nullptr, nullptr, DDIM, 0, bv, nullptr, 0, 1);
    // gate: 1-pass (sigmoid compresses the error)
    gemm3<<<gp, 256, GEMM_SMEM>>>(iqh, iqh, wth[3], wth[3], 0, 0, DDIM, 3,
                                  gate, nullptr, nullptr, DDIM, 0, bg, nullptr, 0, 3);

    // 4. scores = q @ k^T (per batch), full 3-pass
    gemm3<<<dim3(SEQ / 128, SEQ / 128, BB), 256, GEMM_SMEM>>>(
        qh, ql, kh, kl, (long long)SEQ * DDIM, (long long)SEQ * DDIM, DDIM, 0,
        sc, nullptr, nullptr, SEQ, (long long)SEQ * SEQ, nullptr, nullptr, 0, 0);

    // 5. softmax -> fp16 P (register-resident, single read)
    softmax_p<<<MTOT, 256>>>(sc, ph);

    // 6. transpose+split v per batch: [S,D] -> [D,S]
    transpose_split<<<dim3(DDIM / 32, SEQ / 32, BB), tb>>>(
        v, vth, vtl, SEQ, DDIM, (long long)SEQ * DDIM, (long long)SEQ * DDIM);

    // 7. context = (P @ v) * gate -> split; 2-pass, B-residual (P single)
    gemm3<<<dim3(DDIM / 128, SEQ / 128, BB), 256, GEMM_SMEM>>>(
        ph, ph, vth, vtl, (long long)SEQ * SEQ, (long long)DDIM * SEQ, SEQ, 2,
        nullptr, ch, cl, DDIM, (long long)SEQ * DDIM,
        nullptr, gate, (long long)SEQ * DDIM, 4);

    // 8. out = ctx @ Wo + bo; 2-pass, A-residual (ctx split)
    gemm3<<<gp, 256, GEMM_SMEM>>>(ch, cl, wth[4], wtl[4], 0, 0, DDIM, 1,
                                  out, nullptr, nullptr, DDIM, 0, bo, nullptr, 0, 1);
}